// round 12
// baseline (speedup 1.0000x reference)
#include <cuda_runtime.h>
#include <cuda_fp16.h>
#include <math.h>

#define BQ 2
#define LQ 2048
#define KQ 32
#define NRES (BQ*LQ)
#define NWARP 32                 // 1024 threads: 4 residues x 8 warps each
#define CHUNK 28                 // residues per CTA (148*28 = 4144 >= 4096)
#define W_U4 (925*8)             // W_dist fp16 as uint4: 925 rows x 8

// Scratch (allocation-free rule: __device__ globals)
__device__ __align__(16) float  g_petab[65 * 64];     // pe(rel) @ W_pe + b_edge (fp32)
__device__ __align__(16) __half g_wh[925 * 64];       // W_dist in fp16
__device__ __align__(16) float  g_c5[NRES * 16];      // 5 atoms x 3, padded to 16

// packed pair decode: p*37 | (p/5*3)<<16 | (p%5*3)<<24
#define PAIR(p) ((p)*37 | ((p)/5*3)<<16 | ((p)%5*3)<<24)
__constant__ int c_pair[25] = {
    PAIR(0),  PAIR(1),  PAIR(2),  PAIR(3),  PAIR(4),
    PAIR(5),  PAIR(6),  PAIR(7),  PAIR(8),  PAIR(9),
    PAIR(10), PAIR(11), PAIR(12), PAIR(13), PAIR(14),
    PAIR(15), PAIR(16), PAIR(17), PAIR(18), PAIR(19),
    PAIR(20), PAIR(21), PAIR(22), PAIR(23), PAIR(24)
};

// div_term[j] = 10^(-j/8), exact fp32 literals
__constant__ float c_dt[32] = {
    1.0f,            0.74989420f,   0.56234133f,   0.42169650f,
    0.31622777f,     0.23713737f,   0.17782794f,   0.13335214f,
    0.1f,            0.074989420f,  0.056234133f,  0.042169650f,
    0.031622777f,    0.023713737f,  0.017782794f,  0.013335214f,
    0.01f,           0.0074989420f, 0.0056234133f, 0.0042169650f,
    0.0031622777f,   0.0023713737f, 0.0017782794f, 0.0013335214f,
    0.001f,          0.00074989420f,0.00056234133f,0.00042169650f,
    0.00031622777f,  0.00023713737f,0.00017782794f,0.00013335214f
};

__device__ __forceinline__ float sqrt_approx(float s) {
    float d;
    asm("sqrt.approx.f32 %0, %1;" : "=f"(d) : "f"(s));
    return d;
}
__device__ __forceinline__ __half2 H2(unsigned u) { return *(__half2*)&u; }

// ---------------------------------------------------------------------------
// Prologue (one kernel, independent block ranges):
//   blocks [0,65)  : PE table;  [65,81) : coords5;  [81,..) : W fp16 convert
// ---------------------------------------------------------------------------
__global__ void k_prep(const float* __restrict__ W, const float* __restrict__ bvec,
                       const float* __restrict__ coords) {
    int blk = blockIdx.x, tid = threadIdx.x;
    if (blk < 65) {
        if (tid < 64) {
            float rel = (float)(blk - 32);
            float acc = bvec[tid];
            #pragma unroll
            for (int j = 0; j < 32; j++) {
                float ang = rel * c_dt[j];
                acc += __sinf(ang) * W[(925 + 2*j)     * 64 + tid];
                acc += __cosf(ang) * W[(925 + 2*j + 1) * 64 + tid];
            }
            g_petab[blk * 64 + tid] = acc;
        }
    } else if (blk < 81) {
        int r = (blk - 65) * 256 + tid;    // 0..4095
        const float* c = coords + (size_t)r * 12;
        float n0 = c[0], n1 = c[1],  n2 = c[2];
        float a0 = c[3], a1 = c[4],  a2 = c[5];
        float c0 = c[6], c1 = c[7],  c2 = c[8];
        float o0 = c[9], o1 = c[10], o2 = c[11];

        float ux = n0 - a0, uy = n1 - a1, uz = n2 - a2;
        float un = fmaxf(__fsqrt_rn(ux*ux + uy*uy + uz*uz), 1e-12f);
        ux = __fdiv_rn(ux, un); uy = __fdiv_rn(uy, un); uz = __fdiv_rn(uz, un);
        float vx = c0 - a0, vy = c1 - a1, vz = c2 - a2;
        float vn = fmaxf(__fsqrt_rn(vx*vx + vy*vy + vz*vz), 1e-12f);
        vx = __fdiv_rn(vx, vn); vy = __fdiv_rn(vy, vn); vz = __fdiv_rn(vz, vn);
        float bx = ux + vx, by = uy + vy, bz = uz + vz;
        float bn = fmaxf(__fsqrt_rn(bx*bx + by*by + bz*bz), 1e-12f);
        bx = __fdiv_rn(bx, bn); by = __fdiv_rn(by, bn); bz = __fdiv_rn(bz, bn);
        float px = uy*vz - uz*vy;
        float py = uz*vx - ux*vz;
        float pz = ux*vy - uy*vx;
        float pn = fmaxf(__fsqrt_rn(px*px + py*py + pz*pz), 1e-12f);
        px = __fdiv_rn(px, pn); py = __fdiv_rn(py, pn); pz = __fdiv_rn(pz, pn);
        float dx = -bx + 0.5f*px, dy = -by + 0.5f*py, dz = -bz + 0.5f*pz;
        float dn = fmaxf(__fsqrt_rn(dx*dx + dy*dy + dz*dz), 1e-12f);
        dx = __fdiv_rn(dx, dn); dy = __fdiv_rn(dy, dn); dz = __fdiv_rn(dz, dn);

        float4* o4 = (float4*)(g_c5 + (size_t)r * 16);
        o4[0] = make_float4(n0, n1, n2, a0);
        o4[1] = make_float4(a1, a2, c0, c1);
        o4[2] = make_float4(c2, o0, o1, o2);
        o4[3] = make_float4(a0 + 1.54f*dx, a1 + 1.54f*dy, a2 + 1.54f*dz, 0.f);
    } else {
        int i = ((blk - 81) * 256 + tid) * 4;
        if (i < 925 * 64) {
            float4 v = *(const float4*)(W + i);
            __half2 h0 = __floats2half2_rn(v.x, v.y);
            __half2 h1 = __floats2half2_rn(v.z, v.w);
            uint2 u;
            u.x = *(unsigned*)&h0;
            u.y = *(unsigned*)&h1;
            *(uint2*)(g_wh + i) = u;
        }
    }
}

// ---------------------------------------------------------------------------
// Main: PERSISTENT. 148 CTAs x 1024 threads (32 warps), W_dist fp16 resident
// in dynamic smem. 4 residues per iteration (8 warps each); warp-autonomous
// phases (only __syncwarp inside the loop). R11 structure with 2x warps to
// hide LDS latency.
// ---------------------------------------------------------------------------
__global__ void __launch_bounds__(1024)
k_main(const int* __restrict__ nidx, float* __restrict__ out) {
    extern __shared__ __align__(16) uint4 sW[];        // 925 rows x 8 uint4
    __shared__ float s_c5[NWARP][5 * 16];
    __shared__ __align__(16) unsigned short s_rows[NWARP][4][32];

    const int tid  = threadIdx.x;
    const int lane = tid & 31;
    const int w    = tid >> 5;            // 0..31
    const int half = w >> 3;              // residue slot 0..3 within iteration
    const int wl   = w & 7;               // warp-in-slot: owns tuples wl*4..wl*4+3

    // Load W into smem once (coalesced, 1024 threads)
    for (int i = tid; i < W_U4; i += 1024)
        sW[i] = ((const uint4*)g_wh)[i];
    __syncthreads();

    const int e = c_pair[lane < 25 ? lane : 0];
    const int rbase = e & 0xffff;         // p*37
    const int a3 = (e >> 16) & 0xff;      // self atom offset
    const int q3 = e >> 24;               // neighbor atom offset

    const int r0 = blockIdx.x * CHUNK;

    for (int j = 0; j < CHUNK / 4; j++) {
        const int bid = r0 + j * 4 + half;
        if (bid >= NRES) break;
        const int b    = bid >> 11;
        const int l    = bid & (LQ - 1);
        const int base = b * LQ;

        // Phase A: indices + coords (warp-local). Shuffles by ALL lanes.
        int r4 = bid, relreg = 0;
        if (lane < 4) {
            int nb = nidx[bid * KQ + wl * 4 + lane];
            relreg = max(-32, min(32, nb - l)) + 32;
            r4 = base + nb;
        }
        {
            int resid = (lane >> 2) & 7;
            int word  = lane & 3;
            int rsel  = __shfl_sync(0xFFFFFFFFu, r4, resid < 5 ? resid : 4);
            if (lane < 20)
                ((float4*)&s_c5[w][0])[resid * 4 + word] = ((const float4*)g_c5)[rsel * 4 + word];
        }
        __syncwarp();

        // Phase B: 100 distances -> bin rows (u16)
        float sx = s_c5[w][4*16 + a3 + 0];
        float sy = s_c5[w][4*16 + a3 + 1];
        float sz = s_c5[w][4*16 + a3 + 2];
        #pragma unroll
        for (int t = 0; t < 4; t++) {
            float dx = sx - s_c5[w][t*16 + q3 + 0];
            float dy = sy - s_c5[w][t*16 + q3 + 1];
            float dz = sz - s_c5[w][t*16 + q3 + 2];
            float d = sqrt_approx(dx*dx + dy*dy + dz*dz);
            int i = (int)ceilf((d - 2.0f) * 2.0f);   // searchsorted-left, bins 2.0+0.5i
            i = max(0, min(36, i));
            if (lane < 25)
                s_rows[w][t][lane] = (unsigned short)(rbase + i);
        }
        __syncwarp();

        // Phase C: smem gather-accumulate. 8 lanes per tuple, 8 h each.
        const int t  = lane >> 3;
        const int ln = lane & 7;
        const int rel_t = __shfl_sync(0xFFFFFFFFu, relreg, t);

        const float4* __restrict__ P4 = (const float4*)g_petab;
        float4 A0 = P4[rel_t * 16 + 2*ln];
        float4 A1 = P4[rel_t * 16 + 2*ln + 1];

        const unsigned* wp = (const unsigned*)&s_rows[w][t][0];

        #pragma unroll
        for (int g = 0; g < 3; g++) {     // 3 super-groups of 8 rows (LDS.128)
            uint4 ww = *(const uint4*)&wp[4*g];
            uint4 q0 = sW[(ww.x & 0xffffu) * 8 + ln];
            uint4 q1 = sW[(ww.x >> 16)     * 8 + ln];
            uint4 q2 = sW[(ww.y & 0xffffu) * 8 + ln];
            uint4 q3v = sW[(ww.y >> 16)    * 8 + ln];
            __half2 s0 = __hadd2(__hadd2(H2(q0.x), H2(q1.x)), __hadd2(H2(q2.x), H2(q3v.x)));
            __half2 s1 = __hadd2(__hadd2(H2(q0.y), H2(q1.y)), __hadd2(H2(q2.y), H2(q3v.y)));
            __half2 s2 = __hadd2(__hadd2(H2(q0.z), H2(q1.z)), __hadd2(H2(q2.z), H2(q3v.z)));
            __half2 s3 = __hadd2(__hadd2(H2(q0.w), H2(q1.w)), __hadd2(H2(q2.w), H2(q3v.w)));
            uint4 q4 = sW[(ww.z & 0xffffu) * 8 + ln];
            uint4 q5 = sW[(ww.z >> 16)     * 8 + ln];
            uint4 q6 = sW[(ww.w & 0xffffu) * 8 + ln];
            uint4 q7 = sW[(ww.w >> 16)     * 8 + ln];
            s0 = __hadd2(s0, __hadd2(__hadd2(H2(q4.x), H2(q5.x)), __hadd2(H2(q6.x), H2(q7.x))));
            s1 = __hadd2(s1, __hadd2(__hadd2(H2(q4.y), H2(q5.y)), __hadd2(H2(q6.y), H2(q7.y))));
            s2 = __hadd2(s2, __hadd2(__hadd2(H2(q4.z), H2(q5.z)), __hadd2(H2(q6.z), H2(q7.z))));
            s3 = __hadd2(s3, __hadd2(__hadd2(H2(q4.w), H2(q5.w)), __hadd2(H2(q6.w), H2(q7.w))));
            float2 f;
            f = __half22float2(s0); A0.x += f.x; A0.y += f.y;
            f = __half22float2(s1); A0.z += f.x; A0.w += f.y;
            f = __half22float2(s2); A1.x += f.x; A1.y += f.y;
            f = __half22float2(s3); A1.z += f.x; A1.w += f.y;
        }
        {   // leftover 25th row (u16[24])
            uint4 ra = sW[(wp[12] & 0xffffu) * 8 + ln];
            float2 f;
            f = __half22float2(H2(ra.x)); A0.x += f.x; A0.y += f.y;
            f = __half22float2(H2(ra.y)); A0.z += f.x; A0.w += f.y;
            f = __half22float2(H2(ra.z)); A1.x += f.x; A1.y += f.y;
            f = __half22float2(H2(ra.w)); A1.z += f.x; A1.w += f.y;
        }

        float4* out4 = (float4*)out + (size_t)bid * 512;
        const int kk = wl * 4 + t;
        out4[kk * 16 + 2*ln]     = A0;
        out4[kk * 16 + 2*ln + 1] = A1;
        __syncwarp();              // protect s_c5/s_rows reuse next iteration
    }
}

// ---------------------------------------------------------------------------
extern "C" void kernel_launch(void* const* d_in, const int* in_sizes, int n_in,
                              void* d_out, int out_size) {
    const float* coords = (const float*)d_in[0];   // (2,2048,4,3) f32
    const int*   nidx   = (const int*)  d_in[1];   // (2,2048,32) i32
    const float* W      = (const float*)d_in[2];   // (989,64) f32
    const float* bvec   = (const float*)d_in[3];   // (64,) f32

    static const int SMEM = W_U4 * 16;             // 118,400 bytes
    cudaFuncSetAttribute(k_main, cudaFuncAttributeMaxDynamicSharedMemorySize, SMEM);

    k_prep<<<81 + (925*64/4 + 255)/256, 256>>>(W, bvec, coords);
    k_main<<<148, 1024, SMEM>>>(nidx, (float*)d_out);
}

// round 13
// speedup vs baseline: 1.1393x; 1.1393x over previous
#include <cuda_runtime.h>
#include <cuda_fp16.h>
#include <math.h>

#define BQ 2
#define LQ 2048
#define KQ 32
#define NRES (BQ*LQ)

// Scratch (allocation-free rule: __device__ globals)
__device__ __align__(16) float  g_petab[65 * 64];     // pe(rel) @ W_pe + b_edge (fp32)
__device__ __align__(16) __half g_wh[925 * 64];       // W_dist in fp16
__device__ __align__(16) float  g_c5[NRES * 16];      // 5 atoms x 3, padded to 16

// packed pair decode: p*37 | (p/5*3)<<16 | (p%5*3)<<24
#define PAIR(p) ((p)*37 | ((p)/5*3)<<16 | ((p)%5*3)<<24)
__constant__ int c_pair[25] = {
    PAIR(0),  PAIR(1),  PAIR(2),  PAIR(3),  PAIR(4),
    PAIR(5),  PAIR(6),  PAIR(7),  PAIR(8),  PAIR(9),
    PAIR(10), PAIR(11), PAIR(12), PAIR(13), PAIR(14),
    PAIR(15), PAIR(16), PAIR(17), PAIR(18), PAIR(19),
    PAIR(20), PAIR(21), PAIR(22), PAIR(23), PAIR(24)
};

// div_term[j] = 10^(-j/8), exact fp32 literals
__constant__ float c_dt[32] = {
    1.0f,            0.74989420f,   0.56234133f,   0.42169650f,
    0.31622777f,     0.23713737f,   0.17782794f,   0.13335214f,
    0.1f,            0.074989420f,  0.056234133f,  0.042169650f,
    0.031622777f,    0.023713737f,  0.017782794f,  0.013335214f,
    0.01f,           0.0074989420f, 0.0056234133f, 0.0042169650f,
    0.0031622777f,   0.0023713737f, 0.0017782794f, 0.0013335214f,
    0.001f,          0.00074989420f,0.00056234133f,0.00042169650f,
    0.00031622777f,  0.00023713737f,0.00017782794f,0.00013335214f
};

__device__ __forceinline__ float sqrt_approx(float s) {
    float d;
    asm("sqrt.approx.f32 %0, %1;" : "=f"(d) : "f"(s));
    return d;
}
__device__ __forceinline__ __half2 H2(unsigned u) { return *(__half2*)&u; }

// ---------------------------------------------------------------------------
// Prologue (one kernel, independent block ranges):
//   blocks [0,65)  : PE table;  [65,81) : coords5;  [81,..) : W fp16 convert
// ---------------------------------------------------------------------------
__global__ void k_prep(const float* __restrict__ W, const float* __restrict__ bvec,
                       const float* __restrict__ coords) {
    int blk = blockIdx.x, tid = threadIdx.x;
    if (blk < 65) {
        if (tid < 64) {
            float rel = (float)(blk - 32);
            float acc = bvec[tid];
            #pragma unroll
            for (int j = 0; j < 32; j++) {
                float ang = rel * c_dt[j];
                acc += __sinf(ang) * W[(925 + 2*j)     * 64 + tid];
                acc += __cosf(ang) * W[(925 + 2*j + 1) * 64 + tid];
            }
            g_petab[blk * 64 + tid] = acc;
        }
    } else if (blk < 81) {
        int r = (blk - 65) * 256 + tid;    // 0..4095
        const float* c = coords + (size_t)r * 12;
        float n0 = c[0], n1 = c[1],  n2 = c[2];
        float a0 = c[3], a1 = c[4],  a2 = c[5];
        float c0 = c[6], c1 = c[7],  c2 = c[8];
        float o0 = c[9], o1 = c[10], o2 = c[11];

        float ux = n0 - a0, uy = n1 - a1, uz = n2 - a2;
        float un = fmaxf(__fsqrt_rn(ux*ux + uy*uy + uz*uz), 1e-12f);
        ux = __fdiv_rn(ux, un); uy = __fdiv_rn(uy, un); uz = __fdiv_rn(uz, un);
        float vx = c0 - a0, vy = c1 - a1, vz = c2 - a2;
        float vn = fmaxf(__fsqrt_rn(vx*vx + vy*vy + vz*vz), 1e-12f);
        vx = __fdiv_rn(vx, vn); vy = __fdiv_rn(vy, vn); vz = __fdiv_rn(vz, vn);
        float bx = ux + vx, by = uy + vy, bz = uz + vz;
        float bn = fmaxf(__fsqrt_rn(bx*bx + by*by + bz*bz), 1e-12f);
        bx = __fdiv_rn(bx, bn); by = __fdiv_rn(by, bn); bz = __fdiv_rn(bz, bn);
        float px = uy*vz - uz*vy;
        float py = uz*vx - ux*vz;
        float pz = ux*vy - uy*vx;
        float pn = fmaxf(__fsqrt_rn(px*px + py*py + pz*pz), 1e-12f);
        px = __fdiv_rn(px, pn); py = __fdiv_rn(py, pn); pz = __fdiv_rn(pz, pn);
        float dx = -bx + 0.5f*px, dy = -by + 0.5f*py, dz = -bz + 0.5f*pz;
        float dn = fmaxf(__fsqrt_rn(dx*dx + dy*dy + dz*dz), 1e-12f);
        dx = __fdiv_rn(dx, dn); dy = __fdiv_rn(dy, dn); dz = __fdiv_rn(dz, dn);

        float4* o4 = (float4*)(g_c5 + (size_t)r * 16);
        o4[0] = make_float4(n0, n1, n2, a0);
        o4[1] = make_float4(a1, a2, c0, c1);
        o4[2] = make_float4(c2, o0, o1, o2);
        o4[3] = make_float4(a0 + 1.54f*dx, a1 + 1.54f*dy, a2 + 1.54f*dz, 0.f);
    } else {
        int i = ((blk - 81) * 256 + tid) * 4;
        if (i < 925 * 64) {
            float4 v = *(const float4*)(W + i);
            __half2 h0 = __floats2half2_rn(v.x, v.y);
            __half2 h1 = __floats2half2_rn(v.z, v.w);
            uint2 u;
            u.x = *(unsigned*)&h0;
            u.y = *(unsigned*)&h1;
            *(uint2*)(g_wh + i) = u;
        }
    }
}

// ---------------------------------------------------------------------------
// Main: one CTA per (b,l); 256 threads = 8 autonomous warps, 4 tuples each.
// Phases A/B identical to R10. Phase C: 16 lanes per tuple row via LDG.64
// (each load touches 2 lines instead of 4 -> fewer L1tex replays).
//   coords5 slot layout: [0..2]=N [3..5]=CA [6..8]=C [9..11]=O [12..14]=CB
// ---------------------------------------------------------------------------
__global__ void __launch_bounds__(256, 6)
k_main(const int* __restrict__ nidx, float* __restrict__ out) {
    __shared__ float s_c5[8][5 * 16];                  // per-warp: 4 nb + self(4)
    __shared__ __align__(16) unsigned short s_rows[8][4][32];  // 25 used per tuple

    const int tid  = threadIdx.x;
    const int lane = tid & 31;
    const int w    = tid >> 5;
    const int bid  = blockIdx.x;          // = b*L + l
    const int b    = bid >> 11;
    const int l    = bid & (LQ - 1);
    const int base = b * LQ;

    // Phase A: indices + coords (warp-local). Shuffles executed by ALL lanes.
    int r4 = bid, relreg = 0;
    if (lane < 4) {
        int nb = nidx[bid * KQ + w * 4 + lane];
        relreg = max(-32, min(32, nb - l)) + 32;
        r4 = base + nb;
    }
    {
        int resid = (lane >> 2) & 7;      // 0..4 for lanes<20
        int word  = lane & 3;
        int rsel  = __shfl_sync(0xFFFFFFFFu, r4, resid < 5 ? resid : 4);
        if (lane < 20)
            ((float4*)&s_c5[w][0])[resid * 4 + word] = ((const float4*)g_c5)[rsel * 4 + word];
    }
    __syncwarp();

    // Phase B: 100 distances -> bin rows (u16) in warp smem
    int e = c_pair[lane < 25 ? lane : 0];
    int rbase = e & 0xffff;               // p*37
    int a3 = (e >> 16) & 0xff;            // self atom offset
    int q3 = e >> 24;                     // neighbor atom offset
    float sx = s_c5[w][4*16 + a3 + 0];
    float sy = s_c5[w][4*16 + a3 + 1];
    float sz = s_c5[w][4*16 + a3 + 2];
    #pragma unroll
    for (int t = 0; t < 4; t++) {
        float dx = sx - s_c5[w][t*16 + q3 + 0];
        float dy = sy - s_c5[w][t*16 + q3 + 1];
        float dz = sz - s_c5[w][t*16 + q3 + 2];
        float d = sqrt_approx(dx*dx + dy*dy + dz*dz);
        int i = (int)ceilf((d - 2.0f) * 2.0f);   // searchsorted-left, bins 2.0+0.5i
        i = max(0, min(36, i));
        if (lane < 25)
            s_rows[w][t][lane] = (unsigned short)(rbase + i);
    }
    __syncwarp();

    // Phase C: gather-accumulate. 16 lanes per tuple (4 h each, LDG.64 rows);
    // 2 sub-iterations cover the warp's 4 tuples.
    const int tloc = lane >> 4;           // 0/1: tuple within sub-iteration
    const int ln16 = lane & 15;           // h-chunk: halves 4*ln16 .. 4*ln16+3

    const float4* __restrict__ P4 = (const float4*)g_petab;
    const char* __restrict__ Wb = (const char*)g_wh + ln16 * 8;
    float4* out4 = (float4*)out + (size_t)bid * 512;

    #pragma unroll
    for (int s = 0; s < 2; s++) {
        const int t = s * 2 + tloc;       // tuple 0..3
        const int rel_t = __shfl_sync(0xFFFFFFFFu, relreg, t);
        float4 A = P4[rel_t * 16 + ln16];

        const unsigned* wp = (const unsigned*)&s_rows[w][t][0];

        #pragma unroll
        for (int g = 0; g < 3; g++) {     // 8 rows per group
            uint4 ww = *(const uint4*)&wp[4*g];
            uint2 q0 = *(const uint2*)(Wb + (ww.x & 0xffffu) * 128);
            uint2 q1 = *(const uint2*)(Wb + (ww.x >> 16)     * 128);
            uint2 q2 = *(const uint2*)(Wb + (ww.y & 0xffffu) * 128);
            uint2 q3v= *(const uint2*)(Wb + (ww.y >> 16)     * 128);
            __half2 slo = __hadd2(__hadd2(H2(q0.x), H2(q1.x)), __hadd2(H2(q2.x), H2(q3v.x)));
            __half2 shi = __hadd2(__hadd2(H2(q0.y), H2(q1.y)), __hadd2(H2(q2.y), H2(q3v.y)));
            uint2 q4 = *(const uint2*)(Wb + (ww.z & 0xffffu) * 128);
            uint2 q5 = *(const uint2*)(Wb + (ww.z >> 16)     * 128);
            uint2 q6 = *(const uint2*)(Wb + (ww.w & 0xffffu) * 128);
            uint2 q7 = *(const uint2*)(Wb + (ww.w >> 16)     * 128);
            slo = __hadd2(slo, __hadd2(__hadd2(H2(q4.x), H2(q5.x)), __hadd2(H2(q6.x), H2(q7.x))));
            shi = __hadd2(shi, __hadd2(__hadd2(H2(q4.y), H2(q5.y)), __hadd2(H2(q6.y), H2(q7.y))));
            float2 f;
            f = __half22float2(slo); A.x += f.x; A.y += f.y;
            f = __half22float2(shi); A.z += f.x; A.w += f.y;
        }
        {   // leftover 25th row (u16[24])
            uint2 ra = *(const uint2*)(Wb + (wp[12] & 0xffffu) * 128);
            float2 f;
            f = __half22float2(H2(ra.x)); A.x += f.x; A.y += f.y;
            f = __half22float2(H2(ra.y)); A.z += f.x; A.w += f.y;
        }

        const int kk = w * 4 + t;
        out4[kk * 16 + ln16] = A;
    }
}

// ---------------------------------------------------------------------------
extern "C" void kernel_launch(void* const* d_in, const int* in_sizes, int n_in,
                              void* d_out, int out_size) {
    const float* coords = (const float*)d_in[0];   // (2,2048,4,3) f32
    const int*   nidx   = (const int*)  d_in[1];   // (2,2048,32) i32
    const float* W      = (const float*)d_in[2];   // (989,64) f32
    const float* bvec   = (const float*)d_in[3];   // (64,) f32

    k_prep<<<81 + (925*64/4 + 255)/256, 256>>>(W, bvec, coords);
    k_main<<<NRES, 256>>>(nidx, (float*)d_out);
}

// round 14
// speedup vs baseline: 1.1493x; 1.0088x over previous
#include <cuda_runtime.h>
#include <cuda_fp16.h>
#include <math.h>

#define BQ 2
#define LQ 2048
#define KQ 32
#define NRES (BQ*LQ)

// Scratch (allocation-free rule: __device__ globals)
__device__ __align__(16) float  g_petab[65 * 64];     // pe(rel) @ W_pe + b_edge (fp32)
__device__ __align__(16) __half g_wh[925 * 64];       // W_dist in fp16
__device__ __align__(16) float  g_c5[NRES * 16];      // 5 atoms x 3, padded to 16

// packed pair decode: p*37 | (p/5*3)<<16 | (p%5*3)<<24
#define PAIR(p) ((p)*37 | ((p)/5*3)<<16 | ((p)%5*3)<<24)
__constant__ int c_pair[25] = {
    PAIR(0),  PAIR(1),  PAIR(2),  PAIR(3),  PAIR(4),
    PAIR(5),  PAIR(6),  PAIR(7),  PAIR(8),  PAIR(9),
    PAIR(10), PAIR(11), PAIR(12), PAIR(13), PAIR(14),
    PAIR(15), PAIR(16), PAIR(17), PAIR(18), PAIR(19),
    PAIR(20), PAIR(21), PAIR(22), PAIR(23), PAIR(24)
};

// div_term[j] = 10^(-j/8), exact fp32 literals
__constant__ float c_dt[32] = {
    1.0f,            0.74989420f,   0.56234133f,   0.42169650f,
    0.31622777f,     0.23713737f,   0.17782794f,   0.13335214f,
    0.1f,            0.074989420f,  0.056234133f,  0.042169650f,
    0.031622777f,    0.023713737f,  0.017782794f,  0.013335214f,
    0.01f,           0.0074989420f, 0.0056234133f, 0.0042169650f,
    0.0031622777f,   0.0023713737f, 0.0017782794f, 0.0013335214f,
    0.001f,          0.00074989420f,0.00056234133f,0.00042169650f,
    0.00031622777f,  0.00023713737f,0.00017782794f,0.00013335214f
};

__device__ __forceinline__ float sqrt_approx(float s) {
    float d;
    asm("sqrt.approx.f32 %0, %1;" : "=f"(d) : "f"(s));
    return d;
}
__device__ __forceinline__ __half2 H2(unsigned u) { return *(__half2*)&u; }

// ---------------------------------------------------------------------------
// Prologue (one kernel, independent block ranges):
//   blocks [0,17)  : PE table (256 thr/block, 4 rel values each)
//   blocks [17,33) : coords5
//   blocks [33,..) : W fp16 convert
// ---------------------------------------------------------------------------
__global__ void k_prep(const float* __restrict__ W, const float* __restrict__ bvec,
                       const float* __restrict__ coords) {
    int blk = blockIdx.x, tid = threadIdx.x;
    if (blk < 17) {
        int gi  = blk * 256 + tid;
        int rb  = gi >> 6;                 // rel index 0..64
        int h   = gi & 63;
        if (rb < 65) {
            float rel = (float)(rb - 32);
            float acc = bvec[h];
            #pragma unroll
            for (int j = 0; j < 32; j++) {
                float ang = rel * c_dt[j];
                acc += __sinf(ang) * W[(925 + 2*j)     * 64 + h];
                acc += __cosf(ang) * W[(925 + 2*j + 1) * 64 + h];
            }
            g_petab[rb * 64 + h] = acc;
        }
    } else if (blk < 33) {
        int r = (blk - 17) * 256 + tid;    // 0..4095
        const float* c = coords + (size_t)r * 12;
        float n0 = c[0], n1 = c[1],  n2 = c[2];
        float a0 = c[3], a1 = c[4],  a2 = c[5];
        float c0 = c[6], c1 = c[7],  c2 = c[8];
        float o0 = c[9], o1 = c[10], o2 = c[11];

        float ux = n0 - a0, uy = n1 - a1, uz = n2 - a2;
        float un = fmaxf(__fsqrt_rn(ux*ux + uy*uy + uz*uz), 1e-12f);
        ux = __fdiv_rn(ux, un); uy = __fdiv_rn(uy, un); uz = __fdiv_rn(uz, un);
        float vx = c0 - a0, vy = c1 - a1, vz = c2 - a2;
        float vn = fmaxf(__fsqrt_rn(vx*vx + vy*vy + vz*vz), 1e-12f);
        vx = __fdiv_rn(vx, vn); vy = __fdiv_rn(vy, vn); vz = __fdiv_rn(vz, vn);
        float bx = ux + vx, by = uy + vy, bz = uz + vz;
        float bn = fmaxf(__fsqrt_rn(bx*bx + by*by + bz*bz), 1e-12f);
        bx = __fdiv_rn(bx, bn); by = __fdiv_rn(by, bn); bz = __fdiv_rn(bz, bn);
        float px = uy*vz - uz*vy;
        float py = uz*vx - ux*vz;
        float pz = ux*vy - uy*vx;
        float pn = fmaxf(__fsqrt_rn(px*px + py*py + pz*pz), 1e-12f);
        px = __fdiv_rn(px, pn); py = __fdiv_rn(py, pn); pz = __fdiv_rn(pz, pn);
        float dx = -bx + 0.5f*px, dy = -by + 0.5f*py, dz = -bz + 0.5f*pz;
        float dn = fmaxf(__fsqrt_rn(dx*dx + dy*dy + dz*dz), 1e-12f);
        dx = __fdiv_rn(dx, dn); dy = __fdiv_rn(dy, dn); dz = __fdiv_rn(dz, dn);

        float4* o4 = (float4*)(g_c5 + (size_t)r * 16);
        o4[0] = make_float4(n0, n1, n2, a0);
        o4[1] = make_float4(a1, a2, c0, c1);
        o4[2] = make_float4(c2, o0, o1, o2);
        o4[3] = make_float4(a0 + 1.54f*dx, a1 + 1.54f*dy, a2 + 1.54f*dz, 0.f);
    } else {
        int i = ((blk - 33) * 256 + tid) * 4;
        if (i < 925 * 64) {
            float4 v = *(const float4*)(W + i);
            __half2 h0 = __floats2half2_rn(v.x, v.y);
            __half2 h1 = __floats2half2_rn(v.z, v.w);
            uint2 u;
            u.x = *(unsigned*)&h0;
            u.y = *(unsigned*)&h1;
            *(uint2*)(g_wh + i) = u;
        }
    }
}

// ---------------------------------------------------------------------------
// Main: one CTA per (b,l); 256 threads = 8 autonomous warps, 4 tuples each.
// Byte-identical to R13 except launch bounds: (256, 8) -> 32-reg target,
// 64 warps/SM. Phase C: LDG.64, 16 lanes per tuple row (2 lines/instr).
//   coords5 slot layout: [0..2]=N [3..5]=CA [6..8]=C [9..11]=O [12..14]=CB
// ---------------------------------------------------------------------------
__global__ void __launch_bounds__(256, 8)
k_main(const int* __restrict__ nidx, float* __restrict__ out) {
    __shared__ float s_c5[8][5 * 16];                  // per-warp: 4 nb + self(4)
    __shared__ __align__(16) unsigned short s_rows[8][4][32];  // 25 used per tuple

    const int tid  = threadIdx.x;
    const int lane = tid & 31;
    const int w    = tid >> 5;
    const int bid  = blockIdx.x;          // = b*L + l
    const int b    = bid >> 11;
    const int l    = bid & (LQ - 1);
    const int base = b * LQ;

    // Phase A: indices + coords (warp-local). Shuffles executed by ALL lanes.
    int r4 = bid, relreg = 0;
    if (lane < 4) {
        int nb = nidx[bid * KQ + w * 4 + lane];
        relreg = max(-32, min(32, nb - l)) + 32;
        r4 = base + nb;
    }
    {
        int resid = (lane >> 2) & 7;      // 0..4 for lanes<20
        int word  = lane & 3;
        int rsel  = __shfl_sync(0xFFFFFFFFu, r4, resid < 5 ? resid : 4);
        if (lane < 20)
            ((float4*)&s_c5[w][0])[resid * 4 + word] = ((const float4*)g_c5)[rsel * 4 + word];
    }
    __syncwarp();

    // Phase B: 100 distances -> bin rows (u16) in warp smem
    int e = c_pair[lane < 25 ? lane : 0];
    int rbase = e & 0xffff;               // p*37
    int a3 = (e >> 16) & 0xff;            // self atom offset
    int q3 = e >> 24;                     // neighbor atom offset
    float sx = s_c5[w][4*16 + a3 + 0];
    float sy = s_c5[w][4*16 + a3 + 1];
    float sz = s_c5[w][4*16 + a3 + 2];
    #pragma unroll
    for (int t = 0; t < 4; t++) {
        float dx = sx - s_c5[w][t*16 + q3 + 0];
        float dy = sy - s_c5[w][t*16 + q3 + 1];
        float dz = sz - s_c5[w][t*16 + q3 + 2];
        float d = sqrt_approx(dx*dx + dy*dy + dz*dz);
        int i = (int)ceilf((d - 2.0f) * 2.0f);   // searchsorted-left, bins 2.0+0.5i
        i = max(0, min(36, i));
        if (lane < 25)
            s_rows[w][t][lane] = (unsigned short)(rbase + i);
    }
    __syncwarp();

    // Phase C: gather-accumulate. 16 lanes per tuple (4 h each, LDG.64 rows);
    // 2 sub-iterations cover the warp's 4 tuples.
    const int tloc = lane >> 4;           // 0/1: tuple within sub-iteration
    const int ln16 = lane & 15;           // h-chunk: halves 4*ln16 .. 4*ln16+3

    const float4* __restrict__ P4 = (const float4*)g_petab;
    const char* __restrict__ Wb = (const char*)g_wh + ln16 * 8;
    float4* out4 = (float4*)out + (size_t)bid * 512;

    #pragma unroll
    for (int s = 0; s < 2; s++) {
        const int t = s * 2 + tloc;       // tuple 0..3
        const int rel_t = __shfl_sync(0xFFFFFFFFu, relreg, t);
        float4 A = P4[rel_t * 16 + ln16];

        const unsigned* wp = (const unsigned*)&s_rows[w][t][0];

        #pragma unroll
        for (int g = 0; g < 3; g++) {     // 8 rows per group
            uint4 ww = *(const uint4*)&wp[4*g];
            uint2 q0 = *(const uint2*)(Wb + (ww.x & 0xffffu) * 128);
            uint2 q1 = *(const uint2*)(Wb + (ww.x >> 16)     * 128);
            uint2 q2 = *(const uint2*)(Wb + (ww.y & 0xffffu) * 128);
            uint2 q3v= *(const uint2*)(Wb + (ww.y >> 16)     * 128);
            __half2 slo = __hadd2(__hadd2(H2(q0.x), H2(q1.x)), __hadd2(H2(q2.x), H2(q3v.x)));
            __half2 shi = __hadd2(__hadd2(H2(q0.y), H2(q1.y)), __hadd2(H2(q2.y), H2(q3v.y)));
            uint2 q4 = *(const uint2*)(Wb + (ww.z & 0xffffu) * 128);
            uint2 q5 = *(const uint2*)(Wb + (ww.z >> 16)     * 128);
            uint2 q6 = *(const uint2*)(Wb + (ww.w & 0xffffu) * 128);
            uint2 q7 = *(const uint2*)(Wb + (ww.w >> 16)     * 128);
            slo = __hadd2(slo, __hadd2(__hadd2(H2(q4.x), H2(q5.x)), __hadd2(H2(q6.x), H2(q7.x))));
            shi = __hadd2(shi, __hadd2(__hadd2(H2(q4.y), H2(q5.y)), __hadd2(H2(q6.y), H2(q7.y))));
            float2 f;
            f = __half22float2(slo); A.x += f.x; A.y += f.y;
            f = __half22float2(shi); A.z += f.x; A.w += f.y;
        }
        {   // leftover 25th row (u16[24])
            uint2 ra = *(const uint2*)(Wb + (wp[12] & 0xffffu) * 128);
            float2 f;
            f = __half22float2(H2(ra.x)); A.x += f.x; A.y += f.y;
            f = __half22float2(H2(ra.y)); A.z += f.x; A.w += f.y;
        }

        const int kk = w * 4 + t;
        out4[kk * 16 + ln16] = A;
    }
}

// ---------------------------------------------------------------------------
extern "C" void kernel_launch(void* const* d_in, const int* in_sizes, int n_in,
                              void* d_out, int out_size) {
    const float* coords = (const float*)d_in[0];   // (2,2048,4,3) f32
    const int*   nidx   = (const int*)  d_in[1];   // (2,2048,32) i32
    const float* W      = (const float*)d_in[2];   // (989,64) f32
    const float* bvec   = (const float*)d_in[3];   // (64,) f32

    k_prep<<<33 + (925*64/4 + 255)/256, 256>>>(W, bvec, coords);
    k_main<<<NRES, 256>>>(nidx, (float*)d_out);
}